// round 15
// baseline (speedup 1.0000x reference)
#include <cuda_runtime.h>
#include <math.h>
#include <stdint.h>

#define Bv 16
#define Tv 600
#define Hv 512
#define Mv (Bv*Tv)          // 9600 rows
#define G4 (4*Hv)           // 2048 gate rows
#define RS 576              // LSTM smem row stride: 16 k-slices x 36 floats
#define KADDR(k) (((k) >> 5)*36 + ((k) & 31))

// ---------------- scratch (device globals; no allocation) ----------------
__device__ float g_xt [Mv*Hv];
__device__ float g_xpf[Mv*G4];
__device__ float g_xpb[Mv*G4];
__device__ float g_h0 [Mv*2*Hv];
__device__ float g_h1 [Mv*2*Hv];
__device__ float g_fc [Mv*Hv];
__device__ unsigned g_ctrA[64];
__device__ unsigned g_ctrB[64];

// ---------------- helpers ----------------
__device__ __forceinline__ unsigned long long ffma2(unsigned long long a,
                                                    unsigned long long b,
                                                    unsigned long long c)
{
    unsigned long long d;
    asm("fma.rn.f32x2 %0, %1, %2, %3;" : "=l"(d) : "l"(a), "l"(b), "l"(c));
    return d;
}
__device__ __forceinline__ float2 unpk(unsigned long long v)
{
    float2 r;
    asm("mov.b64 {%0, %1}, %2;" : "=f"(r.x), "=f"(r.y) : "l"(v));
    return r;
}
__device__ __forceinline__ unsigned ld_acq(const unsigned* p)
{
    unsigned v;
    asm volatile("ld.acquire.gpu.global.u32 %0, [%1];" : "=r"(v) : "l"(p));
    return v;
}
__device__ __forceinline__ void red_release(unsigned* p)
{
    asm volatile("red.release.gpu.global.add.u32 [%0], 1;" :: "l"(p) : "memory");
}
__device__ __forceinline__ float fast_sig(float x)
{
    return __fdividef(1.f, 1.f + __expf(-x));
}
__device__ __forceinline__ float fast_tanh(float x)
{
    return 1.f - 2.f * __fdividef(1.f, __expf(2.f * x) + 1.f);
}
__device__ __forceinline__ uint32_t su32(const void* p)
{
    uint32_t a;
    asm("{ .reg .u64 t; cvta.to.shared.u64 t, %1; cvt.u32.u64 %0, t; }" : "=r"(a) : "l"(p));
    return a;
}
#define CPA16(dst, src) asm volatile("cp.async.ca.shared.global [%0], [%1], 16;" :: "r"(dst), "l"(src) : "memory")
#define CPA_COMMIT()    asm volatile("cp.async.commit_group;" ::: "memory")
#define CPA_WAIT1()     asm volatile("cp.async.wait_group 1;" ::: "memory")
#define CPA_WAIT0()     asm volatile("cp.async.wait_group 0;" ::: "memory")

// ---------------- transpose x[B,H,T] -> g_xt + counter reset ----------------
__global__ void k_transpose(const float* __restrict__ x)
{
    if (blockIdx.x == 0 && blockIdx.y == 0 && blockIdx.z == 0) {
        int id = threadIdx.y * 32 + threadIdx.x;
        if (id < 64)       g_ctrA[id] = 0u;
        else if (id < 128) g_ctrB[id - 64] = 0u;
    }
    __shared__ float tile[32][33];
    int bb = blockIdx.z;
    int t0 = blockIdx.x * 32, h0 = blockIdx.y * 32;
    int tx = threadIdx.x, ty = threadIdx.y;
    #pragma unroll
    for (int i = 0; i < 4; i++) {
        int hh = h0 + ty + i*8;
        int tt = t0 + tx;
        if (tt < Tv) tile[ty + i*8][tx] = x[(bb*Hv + hh)*Tv + tt];
    }
    __syncthreads();
    #pragma unroll
    for (int i = 0; i < 4; i++) {
        int tt = t0 + ty + i*8;
        int hh = h0 + tx;
        if (tt < Tv) g_xt[(bb*Tv + tt)*Hv + hh] = tile[tx][ty + i*8];
    }
}

// ---------------- persistent GEMM: C[M,N] = A @ W^T + bias ----------------
// BM=128, BN=128, BK=8 double-buffered, 256 threads, 8x8/thread. (R10 proven)
__global__ __launch_bounds__(256, 2) void k_gemm(const float* __restrict__ A,
                                                 int K, int N,
                                                 const float* __restrict__ W1,
                                                 const float* __restrict__ b1,
                                                 float* __restrict__ C1, int nt1,
                                                 const float* __restrict__ W2,
                                                 const float* __restrict__ b2,
                                                 float* __restrict__ C2, int ntot)
{
    __shared__ __align__(16) float As[2][8][132];
    __shared__ __align__(16) float Ws[2][8][132];
    const int tid = threadIdx.x;
    const int tx = tid & 15;
    const int ty = tid >> 4;
    const int lr = tid >> 1;
    const int lk = (tid & 1) * 4;

    for (int t = blockIdx.x; t < ntot; t += gridDim.x) {
        const float* W; const float* bias; float* C; int tt;
        if (t < nt1) { W = W1; bias = b1; C = C1; tt = t; }
        else         { W = W2; bias = b2; C = C2; tt = t - nt1; }
        const int m0 = (tt % 75) * 128;
        const int n0 = (tt / 75) * 128;
        const float* Ap = A + (size_t)(m0 + lr) * K + lk;
        const float* Wp = W + (size_t)(n0 + lr) * K + lk;

        float4 pa = *(const float4*)Ap;
        float4 pw = *(const float4*)Wp;
        As[0][lk+0][lr] = pa.x; As[0][lk+1][lr] = pa.y;
        As[0][lk+2][lr] = pa.z; As[0][lk+3][lr] = pa.w;
        Ws[0][lk+0][lr] = pw.x; Ws[0][lk+1][lr] = pw.y;
        Ws[0][lk+2][lr] = pw.z; Ws[0][lk+3][lr] = pw.w;
        __syncthreads();

        float acc[8][8] = {};
        int cur = 0;
        for (int kb = 8; ; kb += 8) {
            const bool more = kb < K;
            if (more) {
                pa = *(const float4*)(Ap + kb);
                pw = *(const float4*)(Wp + kb);
            }
            #pragma unroll
            for (int k = 0; k < 8; k++) {
                float4 a0 = *(const float4*)&As[cur][k][ty*4];
                float4 a1 = *(const float4*)&As[cur][k][64 + ty*4];
                float4 w0 = *(const float4*)&Ws[cur][k][tx*4];
                float4 w1 = *(const float4*)&Ws[cur][k][64 + tx*4];
                float am[8] = {a0.x,a0.y,a0.z,a0.w,a1.x,a1.y,a1.z,a1.w};
                float wn[8] = {w0.x,w0.y,w0.z,w0.w,w1.x,w1.y,w1.z,w1.w};
                #pragma unroll
                for (int mi = 0; mi < 8; mi++) {
                    #pragma unroll
                    for (int ni = 0; ni < 8; ni++)
                        acc[mi][ni] = fmaf(am[mi], wn[ni], acc[mi][ni]);
                }
            }
            if (!more) break;
            const int nxt = cur ^ 1;
            As[nxt][lk+0][lr] = pa.x; As[nxt][lk+1][lr] = pa.y;
            As[nxt][lk+2][lr] = pa.z; As[nxt][lk+3][lr] = pa.w;
            Ws[nxt][lk+0][lr] = pw.x; Ws[nxt][lk+1][lr] = pw.y;
            Ws[nxt][lk+2][lr] = pw.z; Ws[nxt][lk+3][lr] = pw.w;
            __syncthreads();
            cur = nxt;
        }

        float4 bv0 = *(const float4*)&bias[n0 + tx*4];
        float4 bv1 = *(const float4*)&bias[n0 + 64 + tx*4];
        #pragma unroll
        for (int mi = 0; mi < 8; mi++) {
            int row = m0 + ((mi < 4) ? (ty*4 + mi) : (64 + ty*4 + mi - 4));
            float4 o0, o1;
            o0.x = acc[mi][0] + bv0.x; o0.y = acc[mi][1] + bv0.y;
            o0.z = acc[mi][2] + bv0.z; o0.w = acc[mi][3] + bv0.w;
            o1.x = acc[mi][4] + bv1.x; o1.y = acc[mi][5] + bv1.y;
            o1.z = acc[mi][6] + bv1.z; o1.w = acc[mi][7] + bv1.w;
            *(float4*)&C[(size_t)row*N + n0 + tx*4]      = o0;
            *(float4*)&C[(size_t)row*N + n0 + 64 + tx*4] = o1;
        }
    }
}

// ---------------- persistent bidirectional LSTM (512 threads, A[4][4]) ----------------
// 128 blocks: [0,64) fwd, [64,128) bwd. Block owns 8 hidden units. 16 warps:
// warp wi -> unit u = wi>>1, batch-half bh = wi&1. Lane = bq*16 + ksl: thread
// computes 4 gates x 4 batches (bh*8 + bq*4 + {0..3}) over a 16-k slice per
// phase (cp.async 2-phase reload as R14). Butterfly: scatter batch bits 0,1
// (xor 1,2), allreduce k bits 2,3 (xor 4,8) -> 20 shfl. Act lanes: ksl<4.
__global__ __launch_bounds__(512, 1) void k_lstm(const float* __restrict__ xpf,
                                                 const float* __restrict__ xpb,
                                                 const float* __restrict__ whhf,
                                                 const float* __restrict__ whhb,
                                                 float* __restrict__ hout,
                                                 unsigned* __restrict__ ctrbase)
{
    extern __shared__ float sm[];
    float* w_s = sm;                  // [32][RS]
    float* h_s = w_s + 32*RS;         // [16][RS]

    const int tid   = threadIdx.x;
    const int bid   = blockIdx.x;
    const int dir   = bid >> 6;
    const int u0    = (bid & 63) * 8;
    const float* xp  = dir ? xpb  : xpf;
    const float* whh = dir ? whhb : whhf;
    unsigned* ctr = ctrbase + dir * 32;

    // stage w_hh slice: 32 rows x 512 (row lr: gate=lr>>3, j=lr&7)
    for (int idx = tid; idx < 32*128; idx += 512) {
        int lr = idx >> 7, k = (idx & 127) * 4;
        int gr = (lr >> 3) * 512 + u0 + (lr & 7);
        float4 v = *(const float4*)&whh[(size_t)gr * 512 + k];
        *(float4*)&w_s[lr*RS + KADDR(k)] = v;
    }

    const int lane = tid & 31;
    const int wi   = tid >> 5;        // 0..15
    const int u    = wi >> 1;         // unit slot 0..7
    const int bh   = wi & 1;          // batch half
    const int ksl  = lane & 15;
    const int bq   = lane >> 4;
    // per-phase k offsets (16-wide slices), conflict-free per quarter-warp
    const int kof0 = ((ksl >> 1))*36 + (ksl & 1)*16;
    const int kof1 = (8 + (ksl >> 1))*36 + (ksl & 1)*16;
    const float* wbase = w_s + u*RS;
    const float* hbase = h_s + (bh*8 + bq*4)*RS;

    // cp.async staging addresses (2 chunks per phase per thread)
    uint32_t hdst[2][2];
    size_t   hsrcoff[2][2];
    #pragma unroll
    for (int p = 0; p < 2; p++)
        #pragma unroll
        for (int j = 0; j < 2; j++) {
            int idx = tid + j*512;            // 0..1023
            int bb = idx >> 6, jj = idx & 63;
            int k = p*256 + jj*4;
            hdst[p][j] = su32(&h_s[bb*RS + KADDR(k)]);
            hsrcoff[p][j] = (size_t)bb*Tv*1024 + dir*512 + k;   // + tp*1024
        }

    const bool k0b = (ksl & 1), k1b = (ksl & 2);
    const bool act = (ksl < 4);
    const int  bmy = bh*8 + bq*4 + (ksl & 3);
    const int  unit = u0 + u;
    const size_t xbase = (size_t)bmy*Tv*2048 + unit;            // + t*2048 + g*512
    const size_t hwb   = (size_t)bmy*Tv*1024 + dir*512 + unit;  // + t*1024

    float c = 0.f;
    float xq0=0.f, xq1=0.f, xq2=0.f, xq3=0.f;
    {
        int t0i = dir ? (Tv-1) : 0;
        if (act) {
            const float* p = xp + xbase + (size_t)t0i*2048;
            xq0 = p[0]; xq1 = p[512]; xq2 = p[1024]; xq3 = p[1536];
        }
    }

    for (int s = 0; s < Tv; s++) {
        int t = dir ? (Tv-1 - s) : s;

        unsigned long long A[4][4];
        #pragma unroll
        for (int g = 0; g < 4; g++)
            #pragma unroll
            for (int b = 0; b < 4; b++) A[g][b] = 0ull;

        if (s > 0) {
            if (tid == 0) {
                unsigned target = 64u * (unsigned)s;
                while ((int)(ld_acq(ctr) - target) < 0) { }
            }
            __syncthreads();
            int tp = dir ? t + 1 : t - 1;
            const size_t tterm = (size_t)tp * 1024;
            #pragma unroll
            for (int j = 0; j < 2; j++) CPA16(hdst[0][j], hout + hsrcoff[0][j] + tterm);
            CPA_COMMIT();
            #pragma unroll
            for (int j = 0; j < 2; j++) CPA16(hdst[1][j], hout + hsrcoff[1][j] + tterm);
            CPA_COMMIT();

            // ---- phase 0: k in [0,256) ----
            CPA_WAIT1();
            __syncthreads();
            {
                const float* wg0 = wbase + (0*8)*RS + kof0;
                const float* wg1 = wbase + (1*8)*RS + kof0;
                const float* wg2 = wbase + (2*8)*RS + kof0;
                const float* wg3 = wbase + (3*8)*RS + kof0;
                const float* hb  = hbase + kof0;
                #pragma unroll
                for (int k = 0; k < 16; k += 4) {
                    ulonglong2 w0 = *(const ulonglong2*)&wg0[k];
                    ulonglong2 w1 = *(const ulonglong2*)&wg1[k];
                    ulonglong2 w2 = *(const ulonglong2*)&wg2[k];
                    ulonglong2 w3 = *(const ulonglong2*)&wg3[k];
                    #pragma unroll
                    for (int b = 0; b < 4; b++) {
                        ulonglong2 hv = *(const ulonglong2*)&hb[b*RS + k];
                        A[0][b] = ffma2(hv.x, w0.x, A[0][b]); A[0][b] = ffma2(hv.y, w0.y, A[0][b]);
                        A[1][b] = ffma2(hv.x, w1.x, A[1][b]); A[1][b] = ffma2(hv.y, w1.y, A[1][b]);
                        A[2][b] = ffma2(hv.x, w2.x, A[2][b]); A[2][b] = ffma2(hv.y, w2.y, A[2][b]);
                        A[3][b] = ffma2(hv.x, w3.x, A[3][b]); A[3][b] = ffma2(hv.y, w3.y, A[3][b]);
                    }
                }
            }
            // ---- phase 1: k in [256,512) ----
            CPA_WAIT0();
            __syncthreads();
            {
                const float* wg0 = wbase + (0*8)*RS + kof1;
                const float* wg1 = wbase + (1*8)*RS + kof1;
                const float* wg2 = wbase + (2*8)*RS + kof1;
                const float* wg3 = wbase + (3*8)*RS + kof1;
                const float* hb  = hbase + kof1;
                #pragma unroll
                for (int k = 0; k < 16; k += 4) {
                    ulonglong2 w0 = *(const ulonglong2*)&wg0[k];
                    ulonglong2 w1 = *(const ulonglong2*)&wg1[k];
                    ulonglong2 w2 = *(const ulonglong2*)&wg2[k];
                    ulonglong2 w3 = *(const ulonglong2*)&wg3[k];
                    #pragma unroll
                    for (int b = 0; b < 4; b++) {
                        ulonglong2 hv = *(const ulonglong2*)&hb[b*RS + k];
                        A[0][b] = ffma2(hv.x, w0.x, A[0][b]); A[0][b] = ffma2(hv.y, w0.y, A[0][b]);
                        A[1][b] = ffma2(hv.x, w1.x, A[1][b]); A[1][b] = ffma2(hv.y, w1.y, A[1][b]);
                        A[2][b] = ffma2(hv.x, w2.x, A[2][b]); A[2][b] = ffma2(hv.y, w2.y, A[2][b]);
                        A[3][b] = ffma2(hv.x, w3.x, A[3][b]); A[3][b] = ffma2(hv.y, w3.y, A[3][b]);
                    }
                }
            }
        } else {
            __syncthreads();   // h == 0 at s=0: A stays 0
        }

        float v[4][4];
        #pragma unroll
        for (int g = 0; g < 4; g++)
            #pragma unroll
            for (int b = 0; b < 4; b++) {
                float2 uu = unpk(A[g][b]);
                v[g][b] = uu.x + uu.y;
            }

        // butterfly: scatter batch bit0 (xor1), bit1 (xor2); allreduce k bits (xor4,8)
        float r1[4][2], r2[4];
        #pragma unroll
        for (int g = 0; g < 4; g++)
            #pragma unroll
            for (int j = 0; j < 2; j++) {
                float snd = k0b ? v[g][2*j] : v[g][2*j+1];
                float rcv = __shfl_xor_sync(0xffffffffu, snd, 1);
                r1[g][j] = (k0b ? v[g][2*j+1] : v[g][2*j]) + rcv;
            }
        #pragma unroll
        for (int g = 0; g < 4; g++) {
            float snd = k1b ? r1[g][0] : r1[g][1];
            float rcv = __shfl_xor_sync(0xffffffffu, snd, 2);
            r2[g] = (k1b ? r1[g][1] : r1[g][0]) + rcv;
        }
        #pragma unroll
        for (int g = 0; g < 4; g++) {
            r2[g] += __shfl_xor_sync(0xffffffffu, r2[g], 4);
            r2[g] += __shfl_xor_sync(0xffffffffu, r2[g], 8);
        }

        // prefetch next step's xp (independent of the grid barrier)
        float nx0=0.f, nx1=0.f, nx2=0.f, nx3=0.f;
        if (s + 1 < Tv && act) {
            int tn = dir ? (Tv-2 - s) : (s + 1);
            const float* p = xp + xbase + (size_t)tn*2048;
            nx0 = p[0]; nx1 = p[512]; nx2 = p[1024]; nx3 = p[1536];
        }

        if (act) {
            float gi = r2[0] + xq0;
            float gf = r2[1] + xq1;
            float gg = r2[2] + xq2;
            float go = r2[3] + xq3;
            float iv = fast_sig(gi);
            float fv = fast_sig(gf);
            float gv = fast_tanh(gg);
            float ov = fast_sig(go);
            c = fv * c + iv * gv;
            hout[hwb + (size_t)t*1024] = ov * fast_tanh(c);
        }
        xq0 = nx0; xq1 = nx1; xq2 = nx2; xq3 = nx3;

        // arrive: CTA barrier orders all STGs, then one release-red on counter
        __syncthreads();
        if (tid == 0) red_release(ctr);
    }
}

// ---------------- LayerNorm + ReLU (warp per row of 512) ----------------
__global__ __launch_bounds__(256) void k_lnrelu(const float* __restrict__ in,
                                                const float* __restrict__ lnw,
                                                const float* __restrict__ lnb,
                                                float* __restrict__ out)
{
    int row  = blockIdx.x * 8 + (threadIdx.x >> 5);
    int lane = threadIdx.x & 31;
    const float* p = in + (size_t)row * 512;
    float4 v[4];
    float s = 0.f, s2 = 0.f;
    #pragma unroll
    for (int i = 0; i < 4; i++) {
        v[i] = *(const float4*)&p[i*128 + lane*4];
        s  += v[i].x + v[i].y + v[i].z + v[i].w;
        s2 += v[i].x*v[i].x + v[i].y*v[i].y + v[i].z*v[i].z + v[i].w*v[i].w;
    }
    #pragma unroll
    for (int o = 16; o; o >>= 1) {
        s  += __shfl_xor_sync(0xffffffffu, s,  o);
        s2 += __shfl_xor_sync(0xffffffffu, s2, o);
    }
    float mu   = s * (1.f/512.f);
    float var  = s2 * (1.f/512.f) - mu*mu;
    float rstd = rsqrtf(var + 1e-5f);
    float* q = out + (size_t)row * 512;
    #pragma unroll
    for (int i = 0; i < 4; i++) {
        int k = i*128 + lane*4;
        float4 wv = *(const float4*)&lnw[k];
        float4 bv = *(const float4*)&lnb[k];
        float4 o4;
        o4.x = fmaxf((v[i].x - mu)*rstd*wv.x + bv.x, 0.f);
        o4.y = fmaxf((v[i].y - mu)*rstd*wv.y + bv.y, 0.f);
        o4.z = fmaxf((v[i].z - mu)*rstd*wv.z + bv.z, 0.f);
        o4.w = fmaxf((v[i].w - mu)*rstd*wv.w + bv.w, 0.f);
        *(float4*)&q[k] = o4;
    }
}

// ---------------- host ----------------
extern "C" void kernel_launch(void* const* d_in, const int* in_sizes, int n_in,
                              void* d_out, int out_size)
{
    const float* x       = (const float*)d_in[0];
    const float* wih_l0f = (const float*)d_in[1];
    const float* whh_l0f = (const float*)d_in[2];
    const float* b_l0f   = (const float*)d_in[3];
    const float* wih_l0b = (const float*)d_in[4];
    const float* whh_l0b = (const float*)d_in[5];
    const float* b_l0b   = (const float*)d_in[6];
    const float* wih_l1f = (const float*)d_in[7];
    const float* whh_l1f = (const float*)d_in[8];
    const float* b_l1f   = (const float*)d_in[9];
    const float* wih_l1b = (const float*)d_in[10];
    const float* whh_l1b = (const float*)d_in[11];
    const float* b_l1b   = (const float*)d_in[12];
    const float* fc_w    = (const float*)d_in[13];
    const float* fc_b    = (const float*)d_in[14];
    const float* ln_w    = (const float*)d_in[15];
    const float* ln_b    = (const float*)d_in[16];
    float* out = (float*)d_out;

    void *p_xt, *p_xpf, *p_xpb, *p_h0, *p_h1, *p_fc, *p_cA, *p_cB;
    cudaGetSymbolAddress(&p_xt,  g_xt);
    cudaGetSymbolAddress(&p_xpf, g_xpf);
    cudaGetSymbolAddress(&p_xpb, g_xpb);
    cudaGetSymbolAddress(&p_h0,  g_h0);
    cudaGetSymbolAddress(&p_h1,  g_h1);
    cudaGetSymbolAddress(&p_fc,  g_fc);
    cudaGetSymbolAddress(&p_cA,  g_ctrA);
    cudaGetSymbolAddress(&p_cB,  g_ctrB);

    const size_t LSTM_SMEM = (32*RS + 16*RS) * sizeof(float); // 110592 B
    cudaFuncSetAttribute(k_lstm, cudaFuncAttributeMaxDynamicSharedMemorySize, (int)LSTM_SMEM);

    const int PGRID = 296;

    // 1: transpose input (+ reset both layers' barrier counters)
    k_transpose<<<dim3(19, 16, 16), dim3(32, 8)>>>(x);

    // 2: layer 0 projections, fwd+bwd merged (K=512)
    k_gemm<<<PGRID, 256>>>((const float*)p_xt, 512, 2048,
                           wih_l0f, b_l0f, (float*)p_xpf, 1200,
                           wih_l0b, b_l0b, (float*)p_xpb, 2400);
    // 3: layer 0 recurrence (512 threads/CTA)
    k_lstm<<<128, 512, LSTM_SMEM>>>((const float*)p_xpf, (const float*)p_xpb,
                                    whh_l0f, whh_l0b, (float*)p_h0, (unsigned*)p_cA);
    // 4: layer 1 projections, fwd+bwd merged (K=1024)
    k_gemm<<<PGRID, 256>>>((const float*)p_h0, 1024, 2048,
                           wih_l1f, b_l1f, (float*)p_xpf, 1200,
                           wih_l1b, b_l1b, (float*)p_xpb, 2400);
    // 5: layer 1 recurrence
    k_lstm<<<128, 512, LSTM_SMEM>>>((const float*)p_xpf, (const float*)p_xpb,
                                    whh_l1f, whh_l1b, (float*)p_h1, (unsigned*)p_cB);
    // 6: fc (K=1024, N=512)
    k_gemm<<<PGRID, 256>>>((const float*)p_h1, 1024, 512,
                           fc_w, fc_b, (float*)p_fc, 300,
                           fc_w, fc_b, (float*)p_fc, 300);
    // 7: layernorm + relu
    k_lnrelu<<<1200, 256>>>((const float*)p_fc, ln_w, ln_b, out);
}

// round 16
// speedup vs baseline: 1.0016x; 1.0016x over previous
#include <cuda_runtime.h>
#include <math.h>
#include <stdint.h>

#define Bv 16
#define Tv 600
#define Hv 512
#define Mv (Bv*Tv)          // 9600 rows
#define G4 (4*Hv)           // 2048 gate rows
#define RS 576              // LSTM smem row stride: 16 k-slices x 36 floats
#define KADDR(k) (((k) >> 5)*36 + ((k) & 31))

// ---------------- scratch (device globals; no allocation) ----------------
__device__ float g_xt [Mv*Hv];
__device__ float g_xpf[Mv*G4];
__device__ float g_xpb[Mv*G4];
__device__ float g_h0 [Mv*2*Hv];
__device__ float g_h1 [Mv*2*Hv];
__device__ float g_fc [Mv*Hv];
__device__ unsigned g_ctrA[64];
__device__ unsigned g_ctrB[64];

// ---------------- helpers ----------------
__device__ __forceinline__ unsigned long long ffma2(unsigned long long a,
                                                    unsigned long long b,
                                                    unsigned long long c)
{
    unsigned long long d;
    asm("fma.rn.f32x2 %0, %1, %2, %3;" : "=l"(d) : "l"(a), "l"(b), "l"(c));
    return d;
}
__device__ __forceinline__ float2 unpk(unsigned long long v)
{
    float2 r;
    asm("mov.b64 {%0, %1}, %2;" : "=f"(r.x), "=f"(r.y) : "l"(v));
    return r;
}
__device__ __forceinline__ unsigned ld_acq(const unsigned* p)
{
    unsigned v;
    asm volatile("ld.acquire.gpu.global.u32 %0, [%1];" : "=r"(v) : "l"(p));
    return v;
}
__device__ __forceinline__ void red_release(unsigned* p)
{
    asm volatile("red.release.gpu.global.add.u32 [%0], 1;" :: "l"(p) : "memory");
}
__device__ __forceinline__ float fast_sig(float x)
{
    return __fdividef(1.f, 1.f + __expf(-x));
}
__device__ __forceinline__ float fast_tanh(float x)
{
    return 1.f - 2.f * __fdividef(1.f, __expf(2.f * x) + 1.f);
}
__device__ __forceinline__ uint32_t su32(const void* p)
{
    uint32_t a;
    asm("{ .reg .u64 t; cvta.to.shared.u64 t, %1; cvt.u32.u64 %0, t; }" : "=r"(a) : "l"(p));
    return a;
}
#define CPA16(dst, src) asm volatile("cp.async.ca.shared.global [%0], [%1], 16;" :: "r"(dst), "l"(src) : "memory")
#define CPA_COMMIT()    asm volatile("cp.async.commit_group;" ::: "memory")
#define CPA_WAIT1()     asm volatile("cp.async.wait_group 1;" ::: "memory")
#define CPA_WAIT0()     asm volatile("cp.async.wait_group 0;" ::: "memory")

// ---------------- transpose x[B,H,T] -> g_xt + counter reset ----------------
__global__ void k_transpose(const float* __restrict__ x)
{
    if (blockIdx.x == 0 && blockIdx.y == 0 && blockIdx.z == 0) {
        int id = threadIdx.y * 32 + threadIdx.x;
        if (id < 64)       g_ctrA[id] = 0u;
        else if (id < 128) g_ctrB[id - 64] = 0u;
    }
    __shared__ float tile[32][33];
    int bb = blockIdx.z;
    int t0 = blockIdx.x * 32, h0 = blockIdx.y * 32;
    int tx = threadIdx.x, ty = threadIdx.y;
    #pragma unroll
    for (int i = 0; i < 4; i++) {
        int hh = h0 + ty + i*8;
        int tt = t0 + tx;
        if (tt < Tv) tile[ty + i*8][tx] = x[(bb*Hv + hh)*Tv + tt];
    }
    __syncthreads();
    #pragma unroll
    for (int i = 0; i < 4; i++) {
        int tt = t0 + ty + i*8;
        int hh = h0 + tx;
        if (tt < Tv) g_xt[(bb*Tv + tt)*Hv + hh] = tile[tx][ty + i*8];
    }
}

// ---------------- persistent GEMM: C[M,N] = A @ W^T + bias ----------------
// BM=128, BN=128, BK=8 double-buffered, 256 threads, 8x8/thread. (R10 proven)
__global__ __launch_bounds__(256, 2) void k_gemm(const float* __restrict__ A,
                                                 int K, int N,
                                                 const float* __restrict__ W1,
                                                 const float* __restrict__ b1,
                                                 float* __restrict__ C1, int nt1,
                                                 const float* __restrict__ W2,
                                                 const float* __restrict__ b2,
                                                 float* __restrict__ C2, int ntot)
{
    __shared__ __align__(16) float As[2][8][132];
    __shared__ __align__(16) float Ws[2][8][132];
    const int tid = threadIdx.x;
    const int tx = tid & 15;
    const int ty = tid >> 4;
    const int lr = tid >> 1;
    const int lk = (tid & 1) * 4;

    for (int t = blockIdx.x; t < ntot; t += gridDim.x) {
        const float* W; const float* bias; float* C; int tt;
        if (t < nt1) { W = W1; bias = b1; C = C1; tt = t; }
        else         { W = W2; bias = b2; C = C2; tt = t - nt1; }
        const int m0 = (tt % 75) * 128;
        const int n0 = (tt / 75) * 128;
        const float* Ap = A + (size_t)(m0 + lr) * K + lk;
        const float* Wp = W + (size_t)(n0 + lr) * K + lk;

        float4 pa = *(const float4*)Ap;
        float4 pw = *(const float4*)Wp;
        As[0][lk+0][lr] = pa.x; As[0][lk+1][lr] = pa.y;
        As[0][lk+2][lr] = pa.z; As[0][lk+3][lr] = pa.w;
        Ws[0][lk+0][lr] = pw.x; Ws[0][lk+1][lr] = pw.y;
        Ws[0][lk+2][lr] = pw.z; Ws[0][lk+3][lr] = pw.w;
        __syncthreads();

        float acc[8][8] = {};
        int cur = 0;
        for (int kb = 8; ; kb += 8) {
            const bool more = kb < K;
            if (more) {
                pa = *(const float4*)(Ap + kb);
                pw = *(const float4*)(Wp + kb);
            }
            #pragma unroll
            for (int k = 0; k < 8; k++) {
                float4 a0 = *(const float4*)&As[cur][k][ty*4];
                float4 a1 = *(const float4*)&As[cur][k][64 + ty*4];
                float4 w0 = *(const float4*)&Ws[cur][k][tx*4];
                float4 w1 = *(const float4*)&Ws[cur][k][64 + tx*4];
                float am[8] = {a0.x,a0.y,a0.z,a0.w,a1.x,a1.y,a1.z,a1.w};
                float wn[8] = {w0.x,w0.y,w0.z,w0.w,w1.x,w1.y,w1.z,w1.w};
                #pragma unroll
                for (int mi = 0; mi < 8; mi++) {
                    #pragma unroll
                    for (int ni = 0; ni < 8; ni++)
                        acc[mi][ni] = fmaf(am[mi], wn[ni], acc[mi][ni]);
                }
            }
            if (!more) break;
            const int nxt = cur ^ 1;
            As[nxt][lk+0][lr] = pa.x; As[nxt][lk+1][lr] = pa.y;
            As[nxt][lk+2][lr] = pa.z; As[nxt][lk+3][lr] = pa.w;
            Ws[nxt][lk+0][lr] = pw.x; Ws[nxt][lk+1][lr] = pw.y;
            Ws[nxt][lk+2][lr] = pw.z; Ws[nxt][lk+3][lr] = pw.w;
            __syncthreads();
            cur = nxt;
        }

        float4 bv0 = *(const float4*)&bias[n0 + tx*4];
        float4 bv1 = *(const float4*)&bias[n0 + 64 + tx*4];
        #pragma unroll
        for (int mi = 0; mi < 8; mi++) {
            int row = m0 + ((mi < 4) ? (ty*4 + mi) : (64 + ty*4 + mi - 4));
            float4 o0, o1;
            o0.x = acc[mi][0] + bv0.x; o0.y = acc[mi][1] + bv0.y;
            o0.z = acc[mi][2] + bv0.z; o0.w = acc[mi][3] + bv0.w;
            o1.x = acc[mi][4] + bv1.x; o1.y = acc[mi][5] + bv1.y;
            o1.z = acc[mi][6] + bv1.z; o1.w = acc[mi][7] + bv1.w;
            *(float4*)&C[(size_t)row*N + n0 + tx*4]      = o0;
            *(float4*)&C[(size_t)row*N + n0 + 64 + tx*4] = o1;
        }
    }
}

// ---------------- persistent bidirectional LSTM (R14 + per-warp poll) ----------------
// 128 blocks: [0,64) fwd, [64,128) bwd. Block owns 8 hidden units; warp wi =
// unit. Per step: EVERY warp's lane0 polls the counter (acquire reads), then
// the warp issues its cp.async share immediately (no full-CTA barrier between
// poll and issue). Two commit groups (k<256, k>=256); low-k dot overlaps the
// high-k copy. Reduce-scatter butterfly as R12/R14.
__global__ __launch_bounds__(256, 1) void k_lstm(const float* __restrict__ xpf,
                                                 const float* __restrict__ xpb,
                                                 const float* __restrict__ whhf,
                                                 const float* __restrict__ whhb,
                                                 float* __restrict__ hout,
                                                 unsigned* __restrict__ ctrbase)
{
    extern __shared__ float sm[];
    float* w_s = sm;                  // [32][RS]
    float* h_s = w_s + 32*RS;         // [16][RS]

    const int tid   = threadIdx.x;
    const int bid   = blockIdx.x;
    const int dir   = bid >> 6;
    const int u0    = (bid & 63) * 8;
    const float* xp  = dir ? xpb  : xpf;
    const float* whh = dir ? whhb : whhf;
    unsigned* ctr = ctrbase + dir * 32;

    // stage w_hh slice: 32 rows x 512 (row lr: gate=lr>>3, j=lr&7)
    for (int idx = tid; idx < 32*128; idx += 256) {
        int lr = idx >> 7, k = (idx & 127) * 4;
        int gr = (lr >> 3) * 512 + u0 + (lr & 7);
        float4 v = *(const float4*)&whh[(size_t)gr * 512 + k];
        *(float4*)&w_s[lr*RS + KADDR(k)] = v;
    }

    const int lane = tid & 31;
    const int wi   = tid >> 5;        // unit j = wi
    const int ksl  = lane & 15;
    const int bq   = lane >> 4;
    // per-phase k offsets (16-wide slices), conflict-free per quarter-warp
    const int kof0 = ((ksl >> 1))*36 + (ksl & 1)*16;
    const int kof1 = (8 + (ksl >> 1))*36 + (ksl & 1)*16;
    const float* wbase = w_s + wi*RS;
    const float* hbase = h_s + bq*8*RS;

    // cp.async staging addresses for this thread (4 chunks per phase)
    uint32_t hdst[2][4];
    size_t   hsrcoff[2][4];   // offset into hout minus t-term
    #pragma unroll
    for (int p = 0; p < 2; p++)
        #pragma unroll
        for (int j = 0; j < 4; j++) {
            int idx = tid + j*256;            // 0..1023
            int bb = idx >> 6, jj = idx & 63;
            int k = p*256 + jj*4;
            hdst[p][j] = su32(&h_s[bb*RS + KADDR(k)]);
            hsrcoff[p][j] = (size_t)bb*Tv*1024 + dir*512 + k;   // + tp*1024
        }

    const bool k0b = (ksl & 1), k1b = (ksl & 2), k2b = (ksl & 4);
    const bool act = (lane & 8) == 0;     // ksl < 8
    const int  bmy = bq*8 + (ksl & 7);
    const size_t xbase = (size_t)bmy*Tv*2048 + u0 + wi;            // + t*2048 + g*512
    const size_t hwb   = (size_t)bmy*Tv*1024 + dir*512 + u0 + wi;  // + t*1024

    float c = 0.f;
    float xq0=0.f, xq1=0.f, xq2=0.f, xq3=0.f;
    {
        int t0i = dir ? (Tv-1) : 0;
        if (act) {
            const float* p = xp + xbase + (size_t)t0i*2048;
            xq0 = p[0]; xq1 = p[512]; xq2 = p[1024]; xq3 = p[1536];
        }
    }

    for (int s = 0; s < Tv; s++) {
        int t = dir ? (Tv-1 - s) : s;

        // accumulators (persist across the two k-phases)
        unsigned long long A[4][8];
        #pragma unroll
        for (int g = 0; g < 4; g++)
            #pragma unroll
            for (int b = 0; b < 8; b++) A[g][b] = 0ull;

        if (s > 0) {
            // per-warp poll: lane0 of EVERY warp acquires the counter, then the
            // warp issues its own cp.async share without waiting for the CTA.
            if (lane == 0) {
                unsigned target = 64u * (unsigned)s;
                while ((int)(ld_acq(ctr) - target) < 0) { }
            }
            __syncwarp();
            int tp = dir ? t + 1 : t - 1;
            const size_t tterm = (size_t)tp * 1024;
            #pragma unroll
            for (int j = 0; j < 4; j++) CPA16(hdst[0][j], hout + hsrcoff[0][j] + tterm);
            CPA_COMMIT();
            #pragma unroll
            for (int j = 0; j < 4; j++) CPA16(hdst[1][j], hout + hsrcoff[1][j] + tterm);
            CPA_COMMIT();

            // ---- phase 0: k in [0,256) (copy of phase 1 still in flight) ----
            CPA_WAIT1();
            __syncthreads();
            {
                const float* wg0 = wbase + (0*8)*RS + kof0;
                const float* wg1 = wbase + (1*8)*RS + kof0;
                const float* wg2 = wbase + (2*8)*RS + kof0;
                const float* wg3 = wbase + (3*8)*RS + kof0;
                const float* hb  = hbase + kof0;
                #pragma unroll
                for (int k = 0; k < 16; k += 4) {
                    ulonglong2 w0 = *(const ulonglong2*)&wg0[k];
                    ulonglong2 w1 = *(const ulonglong2*)&wg1[k];
                    ulonglong2 w2 = *(const ulonglong2*)&wg2[k];
                    ulonglong2 w3 = *(const ulonglong2*)&wg3[k];
                    #pragma unroll
                    for (int b = 0; b < 8; b++) {
                        ulonglong2 hv = *(const ulonglong2*)&hb[b*RS + k];
                        A[0][b] = ffma2(hv.x, w0.x, A[0][b]); A[0][b] = ffma2(hv.y, w0.y, A[0][b]);
                        A[1][b] = ffma2(hv.x, w1.x, A[1][b]); A[1][b] = ffma2(hv.y, w1.y, A[1][b]);
                        A[2][b] = ffma2(hv.x, w2.x, A[2][b]); A[2][b] = ffma2(hv.y, w2.y, A[2][b]);
                        A[3][b] = ffma2(hv.x, w3.x, A[3][b]); A[3][b] = ffma2(hv.y, w3.y, A[3][b]);
                    }
                }
            }
            // ---- phase 1: k in [256,512) ----
            CPA_WAIT0();
            __syncthreads();
            {
                const float* wg0 = wbase + (0*8)*RS + kof1;
                const float* wg1 = wbase + (1*8)*RS + kof1;
                const float* wg2 = wbase + (2*8)*RS + kof1;
                const float* wg3 = wbase + (3*8)*RS + kof1;
                const float* hb  = hbase + kof1;
                #pragma unroll
                for (int k = 0; k < 16; k += 4) {
                    ulonglong2 w0 = *(const ulonglong2*)&wg0[k];
                    ulonglong2 w1 = *(const ulonglong2*)&wg1[k];
                    ulonglong2 w2 = *(const ulonglong2*)&wg2[k];
                    ulonglong2 w3 = *(const ulonglong2*)&wg3[k];
                    #pragma unroll
                    for (int b = 0; b < 8; b++) {
                        ulonglong2 hv = *(const ulonglong2*)&hb[b*RS + k];
                        A[0][b] = ffma2(hv.x, w0.x, A[0][b]); A[0][b] = ffma2(hv.y, w0.y, A[0][b]);
                        A[1][b] = ffma2(hv.x, w1.x, A[1][b]); A[1][b] = ffma2(hv.y, w1.y, A[1][b]);
                        A[2][b] = ffma2(hv.x, w2.x, A[2][b]); A[2][b] = ffma2(hv.y, w2.y, A[2][b]);
                        A[3][b] = ffma2(hv.x, w3.x, A[3][b]); A[3][b] = ffma2(hv.y, w3.y, A[3][b]);
                    }
                }
            }
        } else {
            __syncthreads();   // h == 0 at s=0: A stays 0 (also orders w_s staging)
        }

        float v[4][8];
        #pragma unroll
        for (int g = 0; g < 4; g++)
            #pragma unroll
            for (int b = 0; b < 8; b++) {
                float2 u = unpk(A[g][b]);
                v[g][b] = u.x + u.y;
            }

        // reduce-scatter butterfly over ksl (batch bits b0,b1,b2; then allreduce bit3)
        float r1[4][4], r2[4][2], r3[4];
        #pragma unroll
        for (int g = 0; g < 4; g++)
            #pragma unroll
            for (int j = 0; j < 4; j++) {
                float snd = k0b ? v[g][2*j] : v[g][2*j+1];
                float rcv = __shfl_xor_sync(0xffffffffu, snd, 1);
                r1[g][j] = (k0b ? v[g][2*j+1] : v[g][2*j]) + rcv;
            }
        #pragma unroll
        for (int g = 0; g < 4; g++)
            #pragma unroll
            for (int m = 0; m < 2; m++) {
                float snd = k1b ? r1[g][2*m] : r1[g][2*m+1];
                float rcv = __shfl_xor_sync(0xffffffffu, snd, 2);
                r2[g][m] = (k1b ? r1[g][2*m+1] : r1[g][2*m]) + rcv;
            }
        #pragma unroll
        for (int g = 0; g < 4; g++) {
            float snd = k2b ? r2[g][0] : r2[g][1];
            float rcv = __shfl_xor_sync(0xffffffffu, snd, 4);
            r3[g] = (k2b ? r2[g][1] : r2[g][0]) + rcv;
        }
        #pragma unroll
        for (int g = 0; g < 4; g++)
            r3[g] += __shfl_xor_sync(0xffffffffu, r3[g], 8);

        // prefetch next step's xp (independent of the grid barrier)
        float nx0=0.f, nx1=0.f, nx2=0.f, nx3=0.f;
        if (s + 1 < Tv && act) {
            int tn = dir ? (Tv-2 - s) : (s + 1);
            const float* p = xp + xbase + (size_t)tn*2048;
            nx0 = p[0]; nx1 = p[512]; nx2 = p[1024]; nx3 = p[1536];
        }

        if (act) {
            float gi = r3[0] + xq0;
            float gf = r3[1] + xq1;
            float gg = r3[2] + xq2;
            float go = r3[3] + xq3;
            float iv = fast_sig(gi);
            float fv = fast_sig(gf);
            float gv = fast_tanh(gg);
            float ov = fast_sig(go);
            c = fv * c + iv * gv;
            hout[hwb + (size_t)t*1024] = ov * fast_tanh(c);
        }
        xq0 = nx0; xq1 = nx1; xq2 = nx2; xq3 = nx3;

        // arrive: CTA barrier orders all STGs, then one release-red on counter
        __syncthreads();
        if (tid == 0) red_release(ctr);
    }
}

// ---------------- LayerNorm + ReLU (warp per row of 512) ----------------
__global__ __launch_bounds__(256) void k_lnrelu(const float* __restrict__ in,
                                                const float* __restrict__ lnw,
                                                const float* __restrict__ lnb,
                                                float* __restrict__ out)
{
    int row  = blockIdx.x * 8 + (threadIdx.x >> 5);
    int lane = threadIdx.x & 31;
    const float* p = in + (size_t)row * 512;
    float4 v[4];
    float s = 0.f, s2 = 0.f;
    #pragma unroll
    for (int i = 0; i < 4; i++) {
        v[i] = *(const float4*)&p[i*128 + lane*4];
        s  += v[i].x + v[i].y + v[i].z + v[i].w;
        s2 += v[i].x*v[i].x + v[i].y*v[i].y + v[i].z*v[i].z + v[i].w*v[i].w;
    }
    #pragma unroll
    for (int o = 16; o; o >>= 1) {
        s  += __shfl_xor_sync(0xffffffffu, s,  o);
        s2 += __shfl_xor_sync(0xffffffffu, s2, o);
    }
    float mu   = s * (1.f/512.f);
    float var  = s2 * (1.f/512.f) - mu*mu;
    float rstd = rsqrtf(var + 1e-5f);
    float* q = out + (size_t)row * 512;
    #pragma unroll
    for (int i = 0; i < 4; i++) {
        int k = i*128 + lane*4;
        float4 wv = *(const float4*)&lnw[k];
        float4 bv = *(const float4*)&lnb[k];
        float4 o4;
        o4.x = fmaxf((v[i].x - mu)*rstd*wv.x + bv.x, 0.f);
        o4.y = fmaxf((v[i].y - mu)*rstd*wv.y + bv.y, 0.f);
        o4.z = fmaxf((v[i].z - mu)*rstd*wv.z + bv.z, 0.f);
        o4.w = fmaxf((v[i].w - mu)*rstd*wv.w + bv.w, 0.f);
        *(float4*)&q[k] = o4;
    }
}

// ---------------- host ----------------
extern "C" void kernel_launch(void* const* d_in, const int* in_sizes, int n_in,
                              void* d_out, int out_size)
{
    const float* x       = (const float*)d_in[0];
    const float* wih_l0f = (const float*)d_in[1];
    const float* whh_l0f = (const float*)d_in[2];
    const float* b_l0f   = (const float*)d_in[3];
    const float* wih_l0b = (const float*)d_in[4];
    const float* whh_l0b = (const float*)d_in[5];
    const float* b_l0b   = (const float*)d_in[6];
    const float* wih_l1f = (const float*)d_in[7];
    const float* whh_l1f = (const float*)d_in[8];
    const float* b_l1f   = (const float*)d_in[9];
    const float* wih_l1b = (const float*)d_in[10];
    const float* whh_l1b = (const float*)d_in[11];
    const float* b_l1b   = (const float*)d_in[12];
    const float* fc_w    = (const float*)d_in[13];
    const float* fc_b    = (const float*)d_in[14];
    const float* ln_w    = (const float*)d_in[15];
    const float* ln_b    = (const float*)d_in[16];
    float* out = (float*)d_out;

    void *p_xt, *p_xpf, *p_xpb, *p_h0, *p_h1, *p_fc, *p_cA, *p_cB;
    cudaGetSymbolAddress(&p_xt,  g_xt);
    cudaGetSymbolAddress(&p_xpf, g_xpf);
    cudaGetSymbolAddress(&p_xpb, g_xpb);
    cudaGetSymbolAddress(&p_h0,  g_h0);
    cudaGetSymbolAddress(&p_h1,  g_h1);
    cudaGetSymbolAddress(&p_fc,  g_fc);
    cudaGetSymbolAddress(&p_cA,  g_ctrA);
    cudaGetSymbolAddress(&p_cB,  g_ctrB);

    const size_t LSTM_SMEM = (32*RS + 16*RS) * sizeof(float); // 110592 B
    cudaFuncSetAttribute(k_lstm, cudaFuncAttributeMaxDynamicSharedMemorySize, (int)LSTM_SMEM);

    const int PGRID = 296;

    // 1: transpose input (+ reset both layers' barrier counters)
    k_transpose<<<dim3(19, 16, 16), dim3(32, 8)>>>(x);

    // 2: layer 0 projections, fwd+bwd merged (K=512)
    k_gemm<<<PGRID, 256>>>((const float*)p_xt, 512, 2048,
                           wih_l0f, b_l0f, (float*)p_xpf, 1200,
                           wih_l0b, b_l0b, (float*)p_xpb, 2400);
    // 3: layer 0 recurrence
    k_lstm<<<128, 256, LSTM_SMEM>>>((const float*)p_xpf, (const float*)p_xpb,
                                    whh_l0f, whh_l0b, (float*)p_h0, (unsigned*)p_cA);
    // 4: layer 1 projections, fwd+bwd merged (K=1024)
    k_gemm<<<PGRID, 256>>>((const float*)p_h0, 1024, 2048,
                           wih_l1f, b_l1f, (float*)p_xpf, 1200,
                           wih_l1b, b_l1b, (float*)p_xpb, 2400);
    // 5: layer 1 recurrence
    k_lstm<<<128, 256, LSTM_SMEM>>>((const float*)p_xpf, (const float*)p_xpb,
                                    whh_l1f, whh_l1b, (float*)p_h1, (unsigned*)p_cB);
    // 6: fc (K=1024, N=512)
    k_gemm<<<PGRID, 256>>>((const float*)p_h1, 1024, 512,
                           fc_w, fc_b, (float*)p_fc, 300,
                           fc_w, fc_b, (float*)p_fc, 300);
    // 7: layernorm + relu
    k_lnrelu<<<1200, 256>>>((const float*)p_fc, ln_w, ln_b, out);
}

// round 17
// speedup vs baseline: 1.0405x; 1.0388x over previous
#include <cuda_runtime.h>
#include <math.h>
#include <stdint.h>

#define Bv 16
#define Tv 600
#define Hv 512
#define Mv (Bv*Tv)          // 9600 rows
#define G4 (4*Hv)           // 2048 gate rows
#define RS 576              // LSTM smem row stride: 16 k-slices x 36 floats
#define KADDR(k) (((k) >> 5)*36 + ((k) & 31))

// ---------------- scratch (device globals; no allocation) ----------------
__device__ float g_xt [Mv*Hv];
__device__ float g_xpf[Mv*G4];
__device__ float g_xpb[Mv*G4];
__device__ float g_h0 [Mv*2*Hv];
__device__ float g_h1 [Mv*2*Hv];
__device__ float g_fc [Mv*Hv];
__device__ unsigned g_ctrA[64];
__device__ unsigned g_ctrB[64];

// ---------------- helpers ----------------
__device__ __forceinline__ unsigned long long ffma2(unsigned long long a,
                                                    unsigned long long b,
                                                    unsigned long long c)
{
    unsigned long long d;
    asm("fma.rn.f32x2 %0, %1, %2, %3;" : "=l"(d) : "l"(a), "l"(b), "l"(c));
    return d;
}
__device__ __forceinline__ float2 unpk(unsigned long long v)
{
    float2 r;
    asm("mov.b64 {%0, %1}, %2;" : "=f"(r.x), "=f"(r.y) : "l"(v));
    return r;
}
__device__ __forceinline__ unsigned ld_acq(const unsigned* p)
{
    unsigned v;
    asm volatile("ld.acquire.gpu.global.u32 %0, [%1];" : "=r"(v) : "l"(p));
    return v;
}
__device__ __forceinline__ void red_release(unsigned* p)
{
    asm volatile("red.release.gpu.global.add.u32 [%0], 1;" :: "l"(p) : "memory");
}
__device__ __forceinline__ float fast_sig(float x)
{
    return __fdividef(1.f, 1.f + __expf(-x));
}
__device__ __forceinline__ float fast_tanh(float x)
{
    return 1.f - 2.f * __fdividef(1.f, __expf(2.f * x) + 1.f);
}
__device__ __forceinline__ uint32_t su32(const void* p)
{
    uint32_t a;
    asm("{ .reg .u64 t; cvta.to.shared.u64 t, %1; cvt.u32.u64 %0, t; }" : "=r"(a) : "l"(p));
    return a;
}
#define CPA16(dst, src) asm volatile("cp.async.ca.shared.global [%0], [%1], 16;" :: "r"(dst), "l"(src) : "memory")
#define CPA_COMMIT()    asm volatile("cp.async.commit_group;" ::: "memory")
#define CPA_WAIT1()     asm volatile("cp.async.wait_group 1;" ::: "memory")
#define CPA_WAIT0()     asm volatile("cp.async.wait_group 0;" ::: "memory")

// ---------------- transpose x[B,H,T] -> g_xt + counter reset ----------------
__global__ void k_transpose(const float* __restrict__ x)
{
    if (blockIdx.x == 0 && blockIdx.y == 0 && blockIdx.z == 0) {
        int id = threadIdx.y * 32 + threadIdx.x;
        if (id < 64)       g_ctrA[id] = 0u;
        else if (id < 128) g_ctrB[id - 64] = 0u;
    }
    __shared__ float tile[32][33];
    int bb = blockIdx.z;
    int t0 = blockIdx.x * 32, h0 = blockIdx.y * 32;
    int tx = threadIdx.x, ty = threadIdx.y;
    #pragma unroll
    for (int i = 0; i < 4; i++) {
        int hh = h0 + ty + i*8;
        int tt = t0 + tx;
        if (tt < Tv) tile[ty + i*8][tx] = x[(bb*Hv + hh)*Tv + tt];
    }
    __syncthreads();
    #pragma unroll
    for (int i = 0; i < 4; i++) {
        int tt = t0 + ty + i*8;
        int hh = h0 + tx;
        if (tt < Tv) g_xt[(bb*Tv + tt)*Hv + hh] = tile[tx][ty + i*8];
    }
}

// ---------------- persistent GEMM: C[M,N] = A @ W^T + bias ----------------
// BM=128, BN=128, BK=8 double-buffered, 256 threads, 8x8/thread. (R10 proven;
// bias loads hoisted before the k-loop.)
__global__ __launch_bounds__(256, 2) void k_gemm(const float* __restrict__ A,
                                                 int K, int N,
                                                 const float* __restrict__ W1,
                                                 const float* __restrict__ b1,
                                                 float* __restrict__ C1, int nt1,
                                                 const float* __restrict__ W2,
                                                 const float* __restrict__ b2,
                                                 float* __restrict__ C2, int ntot)
{
    __shared__ __align__(16) float As[2][8][132];
    __shared__ __align__(16) float Ws[2][8][132];
    const int tid = threadIdx.x;
    const int tx = tid & 15;
    const int ty = tid >> 4;
    const int lr = tid >> 1;
    const int lk = (tid & 1) * 4;

    for (int t = blockIdx.x; t < ntot; t += gridDim.x) {
        const float* W; const float* bias; float* C; int tt;
        if (t < nt1) { W = W1; bias = b1; C = C1; tt = t; }
        else         { W = W2; bias = b2; C = C2; tt = t - nt1; }
        const int m0 = (tt % 75) * 128;
        const int n0 = (tt / 75) * 128;
        const float* Ap = A + (size_t)(m0 + lr) * K + lk;
        const float* Wp = W + (size_t)(n0 + lr) * K + lk;

        // hoisted bias loads (independent of the k-loop)
        float4 bv0 = *(const float4*)&bias[n0 + tx*4];
        float4 bv1 = *(const float4*)&bias[n0 + 64 + tx*4];

        float4 pa = *(const float4*)Ap;
        float4 pw = *(const float4*)Wp;
        As[0][lk+0][lr] = pa.x; As[0][lk+1][lr] = pa.y;
        As[0][lk+2][lr] = pa.z; As[0][lk+3][lr] = pa.w;
        Ws[0][lk+0][lr] = pw.x; Ws[0][lk+1][lr] = pw.y;
        Ws[0][lk+2][lr] = pw.z; Ws[0][lk+3][lr] = pw.w;
        __syncthreads();

        float acc[8][8] = {};
        int cur = 0;
        for (int kb = 8; ; kb += 8) {
            const bool more = kb < K;
            if (more) {
                pa = *(const float4*)(Ap + kb);
                pw = *(const float4*)(Wp + kb);
            }
            #pragma unroll
            for (int k = 0; k < 8; k++) {
                float4 a0 = *(const float4*)&As[cur][k][ty*4];
                float4 a1 = *(const float4*)&As[cur][k][64 + ty*4];
                float4 w0 = *(const float4*)&Ws[cur][k][tx*4];
                float4 w1 = *(const float4*)&Ws[cur][k][64 + tx*4];
                float am[8] = {a0.x,a0.y,a0.z,a0.w,a1.x,a1.y,a1.z,a1.w};
                float wn[8] = {w0.x,w0.y,w0.z,w0.w,w1.x,w1.y,w1.z,w1.w};
                #pragma unroll
                for (int mi = 0; mi < 8; mi++) {
                    #pragma unroll
                    for (int ni = 0; ni < 8; ni++)
                        acc[mi][ni] = fmaf(am[mi], wn[ni], acc[mi][ni]);
                }
            }
            if (!more) break;
            const int nxt = cur ^ 1;
            As[nxt][lk+0][lr] = pa.x; As[nxt][lk+1][lr] = pa.y;
            As[nxt][lk+2][lr] = pa.z; As[nxt][lk+3][lr] = pa.w;
            Ws[nxt][lk+0][lr] = pw.x; Ws[nxt][lk+1][lr] = pw.y;
            Ws[nxt][lk+2][lr] = pw.z; Ws[nxt][lk+3][lr] = pw.w;
            __syncthreads();
            cur = nxt;
        }

        #pragma unroll
        for (int mi = 0; mi < 8; mi++) {
            int row = m0 + ((mi < 4) ? (ty*4 + mi) : (64 + ty*4 + mi - 4));
            float4 o0, o1;
            o0.x = acc[mi][0] + bv0.x; o0.y = acc[mi][1] + bv0.y;
            o0.z = acc[mi][2] + bv0.z; o0.w = acc[mi][3] + bv0.w;
            o1.x = acc[mi][4] + bv1.x; o1.y = acc[mi][5] + bv1.y;
            o1.z = acc[mi][6] + bv1.z; o1.w = acc[mi][7] + bv1.w;
            *(float4*)&C[(size_t)row*N + n0 + tx*4]      = o0;
            *(float4*)&C[(size_t)row*N + n0 + 64 + tx*4] = o1;
        }
    }
}

// ---------------- persistent bidirectional LSTM (R14 exact + xp hoist) ----------------
// 128 blocks: [0,64) fwd, [64,128) bwd. Block owns 8 hidden units; warp wi =
// unit. Step: tid0 polls counter (one poller/CTA), CTA barrier, all threads
// issue cp.async in two commit groups (k<256, k>=256); low-k dot overlaps
// high-k copy. Reduce-scatter butterfly; one release per CTA.
__global__ __launch_bounds__(256, 1) void k_lstm(const float* __restrict__ xpf,
                                                 const float* __restrict__ xpb,
                                                 const float* __restrict__ whhf,
                                                 const float* __restrict__ whhb,
                                                 float* __restrict__ hout,
                                                 unsigned* __restrict__ ctrbase)
{
    extern __shared__ float sm[];
    float* w_s = sm;                  // [32][RS]
    float* h_s = w_s + 32*RS;         // [16][RS]

    const int tid   = threadIdx.x;
    const int bid   = blockIdx.x;
    const int dir   = bid >> 6;
    const int u0    = (bid & 63) * 8;
    const float* xp  = dir ? xpb  : xpf;
    const float* whh = dir ? whhb : whhf;
    unsigned* ctr = ctrbase + dir * 32;

    // stage w_hh slice: 32 rows x 512 (row lr: gate=lr>>3, j=lr&7)
    for (int idx = tid; idx < 32*128; idx += 256) {
        int lr = idx >> 7, k = (idx & 127) * 4;
        int gr = (lr >> 3) * 512 + u0 + (lr & 7);
        float4 v = *(const float4*)&whh[(size_t)gr * 512 + k];
        *(float4*)&w_s[lr*RS + KADDR(k)] = v;
    }

    const int lane = tid & 31;
    const int wi   = tid >> 5;        // unit j = wi
    const int ksl  = lane & 15;
    const int bq   = lane >> 4;
    // per-phase k offsets (16-wide slices), conflict-free per quarter-warp
    const int kof0 = ((ksl >> 1))*36 + (ksl & 1)*16;
    const int kof1 = (8 + (ksl >> 1))*36 + (ksl & 1)*16;
    const float* wbase = w_s + wi*RS;
    const float* hbase = h_s + bq*8*RS;

    // cp.async staging addresses for this thread (4 chunks per phase)
    uint32_t hdst[2][4];
    size_t   hsrcoff[2][4];   // offset into hout minus t-term
    #pragma unroll
    for (int p = 0; p < 2; p++)
        #pragma unroll
        for (int j = 0; j < 4; j++) {
            int idx = tid + j*256;            // 0..1023
            int bb = idx >> 6, jj = idx & 63;
            int k = p*256 + jj*4;
            hdst[p][j] = su32(&h_s[bb*RS + KADDR(k)]);
            hsrcoff[p][j] = (size_t)bb*Tv*1024 + dir*512 + k;   // + tp*1024
        }

    const bool k0b = (ksl & 1), k1b = (ksl & 2), k2b = (ksl & 4);
    const bool act = (lane & 8) == 0;     // ksl < 8
    const int  bmy = bq*8 + (ksl & 7);
    const size_t xbase = (size_t)bmy*Tv*2048 + u0 + wi;            // + t*2048 + g*512
    const size_t hwb   = (size_t)bmy*Tv*1024 + dir*512 + u0 + wi;  // + t*1024

    float c = 0.f;
    float xq0=0.f, xq1=0.f, xq2=0.f, xq3=0.f;
    {
        int t0i = dir ? (Tv-1) : 0;
        if (act) {
            const float* p = xp + xbase + (size_t)t0i*2048;
            xq0 = p[0]; xq1 = p[512]; xq2 = p[1024]; xq3 = p[1536];
        }
    }

    for (int s = 0; s < Tv; s++) {
        int t = dir ? (Tv-1 - s) : s;

        // accumulators (persist across the two k-phases)
        unsigned long long A[4][8];
        #pragma unroll
        for (int g = 0; g < 4; g++)
            #pragma unroll
            for (int b = 0; b < 8; b++) A[g][b] = 0ull;

        if (s > 0) {
            if (tid == 0) {
                unsigned target = 64u * (unsigned)s;
                while ((int)(ld_acq(ctr) - target) < 0) { }
            }
            __syncthreads();
            int tp = dir ? t + 1 : t - 1;
            const size_t tterm = (size_t)tp * 1024;
            // issue both phases' copies as two groups
            #pragma unroll
            for (int j = 0; j < 4; j++) CPA16(hdst[0][j], hout + hsrcoff[0][j] + tterm);
            CPA_COMMIT();
            #pragma unroll
            for (int j = 0; j < 4; j++) CPA16(hdst[1][j], hout + hsrcoff[1][j] + tterm);
            CPA_COMMIT();

            // ---- phase 0: k in [0,256) (copy of phase 1 still in flight) ----
            CPA_WAIT1();
            __syncthreads();
            {
                const float* wg0 = wbase + (0*8)*RS + kof0;
                const float* wg1 = wbase + (1*8)*RS + kof0;
                const float* wg2 = wbase + (2*8)*RS + kof0;
                const float* wg3 = wbase + (3*8)*RS + kof0;
                const float* hb  = hbase + kof0;
                #pragma unroll
                for (int k = 0; k < 16; k += 4) {
                    ulonglong2 w0 = *(const ulonglong2*)&wg0[k];
                    ulonglong2 w1 = *(const ulonglong2*)&wg1[k];
                    ulonglong2 w2 = *(const ulonglong2*)&wg2[k];
                    ulonglong2 w3 = *(const ulonglong2*)&wg3[k];
                    #pragma unroll
                    for (int b = 0; b < 8; b++) {
                        ulonglong2 hv = *(const ulonglong2*)&hb[b*RS + k];
                        A[0][b] = ffma2(hv.x, w0.x, A[0][b]); A[0][b] = ffma2(hv.y, w0.y, A[0][b]);
                        A[1][b] = ffma2(hv.x, w1.x, A[1][b]); A[1][b] = ffma2(hv.y, w1.y, A[1][b]);
                        A[2][b] = ffma2(hv.x, w2.x, A[2][b]); A[2][b] = ffma2(hv.y, w2.y, A[2][b]);
                        A[3][b] = ffma2(hv.x, w3.x, A[3][b]); A[3][b] = ffma2(hv.y, w3.y, A[3][b]);
                    }
                }
            }
            // ---- phase 1: k in [256,512) ----
            CPA_WAIT0();
            __syncthreads();
            {
                const float* wg0 = wbase + (0*8)*RS + kof1;
                const float* wg1 = wbase + (1*8)*RS + kof1;
                const float* wg2 = wbase + (2*8)*RS + kof1;
                const float* wg3 = wbase + (3*8)*RS + kof1;
                const float* hb  = hbase + kof1;
                #pragma unroll
                for (int k = 0; k < 16; k += 4) {
                    ulonglong2 w0 = *(const ulonglong2*)&wg0[k];
                    ulonglong2 w1 = *(const ulonglong2*)&wg1[k];
                    ulonglong2 w2 = *(const ulonglong2*)&wg2[k];
                    ulonglong2 w3 = *(const ulonglong2*)&wg3[k];
                    #pragma unroll
                    for (int b = 0; b < 8; b++) {
                        ulonglong2 hv = *(const ulonglong2*)&hb[b*RS + k];
                        A[0][b] = ffma2(hv.x, w0.x, A[0][b]); A[0][b] = ffma2(hv.y, w0.y, A[0][b]);
                        A[1][b] = ffma2(hv.x, w1.x, A[1][b]); A[1][b] = ffma2(hv.y, w1.y, A[1][b]);
                        A[2][b] = ffma2(hv.x, w2.x, A[2][b]); A[2][b] = ffma2(hv.y, w2.y, A[2][b]);
                        A[3][b] = ffma2(hv.x, w3.x, A[3][b]); A[3][b] = ffma2(hv.y, w3.y, A[3][b]);
                    }
                }
            }
        } else {
            __syncthreads();   // h == 0 at s=0: A stays 0 (also orders w_s staging)
        }

        // prefetch next step's xp EARLY (independent of reduction; hides LDG
        // latency under the butterfly below)
        float nx0=0.f, nx1=0.f, nx2=0.f, nx3=0.f;
        if (s + 1 < Tv && act) {
            int tn = dir ? (Tv-2 - s) : (s + 1);
            const float* p = xp + xbase + (size_t)tn*2048;
            nx0 = p[0]; nx1 = p[512]; nx2 = p[1024]; nx3 = p[1536];
        }

        float v[4][8];
        #pragma unroll
        for (int g = 0; g < 4; g++)
            #pragma unroll
            for (int b = 0; b < 8; b++) {
                float2 u = unpk(A[g][b]);
                v[g][b] = u.x + u.y;
            }

        // reduce-scatter butterfly over ksl (batch bits b0,b1,b2; then allreduce bit3)
        float r1[4][4], r2[4][2], r3[4];
        #pragma unroll
        for (int g = 0; g < 4; g++)
            #pragma unroll
            for (int j = 0; j < 4; j++) {
                float snd = k0b ? v[g][2*j] : v[g][2*j+1];
                float rcv = __shfl_xor_sync(0xffffffffu, snd, 1);
                r1[g][j] = (k0b ? v[g][2*j+1] : v[g][2*j]) + rcv;
            }
        #pragma unroll
        for (int g = 0; g < 4; g++)
            #pragma unroll
            for (int m = 0; m < 2; m++) {
                float snd = k1b ? r1[g][2*m] : r1[g][2*m+1];
                float rcv = __shfl_xor_sync(0xffffffffu, snd, 2);
                r2[g][m] = (k1b ? r1[g][2*m+1] : r1[g][2*m]) + rcv;
            }
        #pragma unroll
        for (int g = 0; g < 4; g++) {
            float snd = k2b ? r2[g][0] : r2[g][1];
            float rcv = __shfl_xor_sync(0xffffffffu, snd, 4);
            r3[g] = (k2b ? r2[g][1] : r2[g][0]) + rcv;
        }
        #pragma unroll
        for (int g = 0; g < 4; g++)
            r3[g] += __shfl_xor_sync(0xffffffffu, r3[g], 8);

        if (act) {
            float gi = r3[0] + xq0;
            float gf = r3[1] + xq1;
            float gg = r3[2] + xq2;
            float go = r3[3] + xq3;
            float iv = fast_sig(gi);
            float fv = fast_sig(gf);
            float gv = fast_tanh(gg);
            float ov = fast_sig(go);
            c = fv * c + iv * gv;
            hout[hwb + (size_t)t*1024] = ov * fast_tanh(c);
        }
        xq0 = nx0; xq1 = nx1; xq2 = nx2; xq3 = nx3;

        // arrive: CTA barrier orders all STGs, then one release-red on counter
        __syncthreads();
        if (tid == 0) red_release(ctr);
    }
}

// ---------------- LayerNorm + ReLU (warp per row of 512) ----------------
__global__ __launch_bounds__(256) void k_lnrelu(const float* __restrict__ in,
                                                const float* __restrict__ lnw,
                                                const float* __restrict__ lnb,
                                                float* __restrict__ out)
{
    int row  = blockIdx.x * 8 + (threadIdx.x >> 5);
    int lane = threadIdx.x & 31;
    const float* p = in + (size_t)row * 512;
    float4 v[4];
    float s = 0.f, s2 = 0.f;
    #pragma unroll
    for (int i = 0; i < 4; i++) {
        v[i] = *(const float4*)&p[i*128 + lane*4];
        s  += v[i].x + v[i].y + v[i].z + v[i].w;
        s2 += v[i].x*v[i].x + v[i].y*v[i].y + v[i].z*v[i].z + v[i].w*v[i].w;
    }
    #pragma unroll
    for (int o = 16; o; o >>= 1) {
        s  += __shfl_xor_sync(0xffffffffu, s,  o);
        s2 += __shfl_xor_sync(0xffffffffu, s2, o);
    }
    float mu   = s * (1.f/512.f);
    float var  = s2 * (1.f/512.f) - mu*mu;
    float rstd = rsqrtf(var + 1e-5f);
    float* q = out + (size_t)row * 512;
    #pragma unroll
    for (int i = 0; i < 4; i++) {
        int k = i*128 + lane*4;
        float4 wv = *(const float4*)&lnw[k];
        float4 bv = *(const float4*)&lnb[k];
        float4 o4;
        o4.x = fmaxf((v[i].x - mu)*rstd*wv.x + bv.x, 0.f);
        o4.y = fmaxf((v[i].y - mu)*rstd*wv.y + bv.y, 0.f);
        o4.z = fmaxf((v[i].z - mu)*rstd*wv.z + bv.z, 0.f);
        o4.w = fmaxf((v[i].w - mu)*rstd*wv.w + bv.w, 0.f);
        *(float4*)&q[k] = o4;
    }
}

// ---------------- host ----------------
extern "C" void kernel_launch(void* const* d_in, const int* in_sizes, int n_in,
                              void* d_out, int out_size)
{
    const float* x       = (const float*)d_in[0];
    const float* wih_l0f = (const float*)d_in[1];
    const float* whh_l0f = (const float*)d_in[2];
    const float* b_l0f   = (const float*)d_in[3];
    const float* wih_l0b = (const float*)d_in[4];
    const float* whh_l0b = (const float*)d_in[5];
    const float* b_l0b   = (const float*)d_in[6];
    const float* wih_l1f = (const float*)d_in[7];
    const float* whh_l1f = (const float*)d_in[8];
    const float* b_l1f   = (const float*)d_in[9];
    const float* wih_l1b = (const float*)d_in[10];
    const float* whh_l1b = (const float*)d_in[11];
    const float* b_l1b   = (const float*)d_in[12];
    const float* fc_w    = (const float*)d_in[13];
    const float* fc_b    = (const float*)d_in[14];
    const float* ln_w    = (const float*)d_in[15];
    const float* ln_b    = (const float*)d_in[16];
    float* out = (float*)d_out;

    void *p_xt, *p_xpf, *p_xpb, *p_h0, *p_h1, *p_fc, *p_cA, *p_cB;
    cudaGetSymbolAddress(&p_xt,  g_xt);
    cudaGetSymbolAddress(&p_xpf, g_xpf);
    cudaGetSymbolAddress(&p_xpb, g_xpb);
    cudaGetSymbolAddress(&p_h0,  g_h0);
    cudaGetSymbolAddress(&p_h1,  g_h1);
    cudaGetSymbolAddress(&p_fc,  g_fc);
    cudaGetSymbolAddress(&p_cA,  g_ctrA);
    cudaGetSymbolAddress(&p_cB,  g_ctrB);

    const size_t LSTM_SMEM = (32*RS + 16*RS) * sizeof(float); // 110592 B
    cudaFuncSetAttribute(k_lstm, cudaFuncAttributeMaxDynamicSharedMemorySize, (int)LSTM_SMEM);

    const int PGRID = 296;

    // 1: transpose input (+ reset both layers' barrier counters)
    k_transpose<<<dim3(19, 16, 16), dim3(32, 8)>>>(x);

    // 2: layer 0 projections, fwd+bwd merged (K=512)
    k_gemm<<<PGRID, 256>>>((const float*)p_xt, 512, 2048,
                           wih_l0f, b_l0f, (float*)p_xpf, 1200,
                           wih_l0b, b_l0b, (float*)p_xpb, 2400);
    // 3: layer 0 recurrence
    k_lstm<<<128, 256, LSTM_SMEM>>>((const float*)p_xpf, (const float*)p_xpb,
                                    whh_l0f, whh_l0b, (float*)p_h0, (unsigned*)p_cA);
    // 4: layer 1 projections, fwd+bwd merged (K=1024)
    k_gemm<<<PGRID, 256>>>((const float*)p_h0, 1024, 2048,
                           wih_l1f, b_l1f, (float*)p_xpf, 1200,
                           wih_l1b, b_l1b, (float*)p_xpb, 2400);
    // 5: layer 1 recurrence
    k_lstm<<<128, 256, LSTM_SMEM>>>((const float*)p_xpf, (const float*)p_xpb,
                                    whh_l1f, whh_l1b, (float*)p_h1, (unsigned*)p_cB);
    // 6: fc (K=1024, N=512)
    k_gemm<<<PGRID, 256>>>((const float*)p_h1, 1024, 512,
                           fc_w, fc_b, (float*)p_fc, 300,
                           fc_w, fc_b, (float*)p_fc, 300);
    // 7: layernorm + relu
    k_lnrelu<<<1200, 256>>>((const float*)p_fc, ln_w, ln_b, out);
}